// round 16
// baseline (speedup 1.0000x reference)
#include <cuda_runtime.h>
#include <cuda_bf16.h>
#include <stdint.h>
#include <math.h>

#define NWIN 32
#define BHN  32
#define LSEQ 4096
#define HDIM 64

#define SWZC(row, c) (((uint32_t)(row)) * 128u + ((((uint32_t)(c)) ^ (((uint32_t)(row)) & 7u)) << 4))

// ---- smem layout (bytes) ----
#define OFF_QH  0u            // 128x64 bf16 swizzled (16KB)
#define OFF_KV  16384u        // 3 pair-slots x 32KB; pair-slot = 2 blocks x (KH,KL,VH,VL x 4KB)
#define TILEB   4096u
#define BLKB    16384u        // one block = 4 tiles
#define PSLOTB  32768u        // pair-slot = 2 blocks
#define OFF_MB  114688u       // 6 mbarriers (full[3], empty[3])
#define SMEM_TOT 114752u

// ---- global scratch: pre-converted bf16 hi/lo K and V ----
#define KVBYTES (32ull * 4096ull * 64ull * 2ull)
__device__ __align__(16) unsigned char g_KH[KVBYTES];
__device__ __align__(16) unsigned char g_KL[KVBYTES];
__device__ __align__(16) unsigned char g_VH[KVBYTES];
__device__ __align__(16) unsigned char g_VL[KVBYTES];

static __device__ __forceinline__ uint32_t smem_u32(const void* p) {
    uint32_t a;
    asm("{ .reg .u64 t; cvta.to.shared.u64 t, %1; cvt.u32.u64 %0, t; }" : "=r"(a) : "l"(p));
    return a;
}
static __device__ __forceinline__ void ldsm4(uint32_t r[4], uint32_t a) {
    asm volatile("ldmatrix.sync.aligned.m8n8.x4.shared.b16 {%0,%1,%2,%3}, [%4];"
                 : "=r"(r[0]), "=r"(r[1]), "=r"(r[2]), "=r"(r[3]) : "r"(a));
}
static __device__ __forceinline__ void ldsm4t(uint32_t r[4], uint32_t a) {
    asm volatile("ldmatrix.sync.aligned.m8n8.x4.trans.shared.b16 {%0,%1,%2,%3}, [%4];"
                 : "=r"(r[0]), "=r"(r[1]), "=r"(r[2]), "=r"(r[3]) : "r"(a));
}
static __device__ __forceinline__ void mma16816(float* c, const uint32_t* a, const uint32_t* b) {
    asm volatile("mma.sync.aligned.m16n8k16.row.col.f32.bf16.bf16.f32 "
                 "{%0,%1,%2,%3}, {%4,%5,%6,%7}, {%8,%9}, {%0,%1,%2,%3};"
                 : "+f"(c[0]), "+f"(c[1]), "+f"(c[2]), "+f"(c[3])
                 : "r"(a[0]), "r"(a[1]), "r"(a[2]), "r"(a[3]), "r"(b[0]), "r"(b[1]));
}
static __device__ __forceinline__ float ex2f(float x) {
    float r; asm("ex2.approx.ftz.f32 %0, %1;" : "=f"(r) : "f"(x)); return r;
}
#define CP16(d, s)   asm volatile("cp.async.cg.shared.global [%0], [%1], 16;" :: "r"(d), "l"(s))
#define CPARR(a)     asm volatile("cp.async.mbarrier.arrive.noinc.shared.b64 [%0];" :: "r"(a) : "memory")
#define MARR(a)      asm volatile("mbarrier.arrive.shared.b64 _, [%0];" :: "r"(a) : "memory")
#define MBINIT(a, n) asm volatile("mbarrier.init.shared.b64 [%0], %1;" :: "r"(a), "r"(n) : "memory")

static __device__ __forceinline__ void mbar_wait(uint32_t a, uint32_t parity) {
    uint32_t done;
    asm volatile(
        "{ .reg .pred p; mbarrier.try_wait.parity.acquire.cta.shared::cta.b64 p, [%1], %2;"
        " selp.b32 %0, 1, 0, p; }"
        : "=r"(done) : "r"(a), "r"(parity) : "memory");
    if (!done) {
        asm volatile(
            "{ .reg .pred P1;\n"
            "WL%=: mbarrier.try_wait.parity.acquire.cta.shared::cta.b64 P1, [%0], %1, 0x989680;\n"
            "@P1 bra.uni WD%=;\n"
            "bra.uni WL%=;\n"
            "WD%=: }"
            :: "r"(a), "r"(parity) : "memory");
    }
}

static __device__ __forceinline__ void split2(float a, float b, uint32_t& hi, uint32_t& lo) {
    __nv_bfloat16 ha = __float2bfloat16_rn(a), hb = __float2bfloat16_rn(b);
    float ra = a - __bfloat162float(ha), rb = b - __bfloat162float(hb);
    __nv_bfloat16 la = __float2bfloat16_rn(ra), lb = __float2bfloat16_rn(rb);
    hi = (uint32_t)__bfloat16_as_ushort(ha) | ((uint32_t)__bfloat16_as_ushort(hb) << 16);
    lo = (uint32_t)__bfloat16_as_ushort(la) | ((uint32_t)__bfloat16_as_ushort(lb) << 16);
}
static __device__ __forceinline__ void cvt8(const float* v, uint4& h, uint4& l) {
    uint32_t hh[4], ll[4];
#pragma unroll
    for (int j = 0; j < 4; j++) split2(v[2 * j], v[2 * j + 1], hh[j], ll[j]);
    h = make_uint4(hh[0], hh[1], hh[2], hh[3]);
    l = make_uint4(ll[0], ll[1], ll[2], ll[3]);
}

// ---------------- pre-pass: K/V f32 -> bf16 hi/lo in global scratch ----------------
__global__ void __launch_bounds__(256)
conv_kv(const float* __restrict__ K, const float* __restrict__ V)
{
    size_t id = (size_t)blockIdx.x * 256 + threadIdx.x;
    {
        const float4* kp = (const float4*)(K + id * 8);
        float4 A = kp[0], B = kp[1];
        float v[8] = {A.x, A.y, A.z, A.w, B.x, B.y, B.z, B.w};
        uint4 h, l; cvt8(v, h, l);
        *(uint4*)(g_KH + id * 16) = h;
        *(uint4*)(g_KL + id * 16) = l;
    }
    {
        const float4* vp = (const float4*)(V + id * 8);
        float4 A = vp[0], B = vp[1];
        float v[8] = {A.x, A.y, A.z, A.w, B.x, B.y, B.z, B.w};
        uint4 h, l; cvt8(v, h, l);
        *(uint4*)(g_VH + id * 16) = h;
        *(uint4*)(g_VL + id * 16) = l;
    }
}

static __device__ __forceinline__ int colof(int i, int w) {
    return (i < w) ? (4 * i + 3) : (4 * w + (i - w));
}

// one K-dim step (16 of 64) of QK for one block: 4 LDSM + 12 HMMA
static __device__ __forceinline__ void qk_step(float sc[4][4], uint32_t slot,
                                               uint32_t krow0, uint32_t krow1, uint32_t kxc,
                                               int kt, const uint32_t qh[4][4],
                                               const uint32_t ql[4][4]) {
    uint32_t c0 = kxc + 2u * (uint32_t)kt;
    uint32_t a0 = slot + krow0 * 128u + ((c0 ^ (krow0 & 7u)) << 4);
    uint32_t a1 = slot + krow1 * 128u + ((c0 ^ (krow1 & 7u)) << 4);
    uint32_t bh0[4], bh1[4], bl0[4], bl1[4];
    ldsm4(bh0, a0);
    ldsm4(bh1, a1);
    ldsm4(bl0, a0 + TILEB);
    ldsm4(bl1, a1 + TILEB);
    mma16816(sc[0], qh[kt], &bh0[0]);  mma16816(sc[1], qh[kt], &bh0[2]);
    mma16816(sc[2], qh[kt], &bh1[0]);  mma16816(sc[3], qh[kt], &bh1[2]);
    mma16816(sc[0], qh[kt], &bl0[0]);  mma16816(sc[1], qh[kt], &bl0[2]);
    mma16816(sc[2], qh[kt], &bl1[0]);  mma16816(sc[3], qh[kt], &bl1[2]);
    mma16816(sc[0], ql[kt], &bh0[0]);  mma16816(sc[1], ql[kt], &bh0[2]);
    mma16816(sc[2], ql[kt], &bh1[0]);  mma16816(sc[3], ql[kt], &bh1[2]);
}
static __device__ __forceinline__ void qk_block(float sc[4][4], uint32_t slot,
                                                uint32_t krow0, uint32_t krow1, uint32_t kxc,
                                                const uint32_t qh[4][4], const uint32_t ql[4][4]) {
#pragma unroll
    for (int kt = 0; kt < 4; kt++) qk_step(sc, slot, krow0, krow1, kxc, kt, qh, ql);
}

static __device__ __forceinline__ void exp4(float* s, float& l0, float& l1) {
    s[0] = ex2f(s[0]); s[1] = ex2f(s[1]);
    s[2] = ex2f(s[2]); s[3] = ex2f(s[3]);
    l0 += s[0] + s[1]; l1 += s[2] + s[3];
}
static __device__ __forceinline__ void split8(const float sc[4][4],
                                              uint32_t ph[2][4], uint32_t pl[2][4]) {
#pragma unroll
    for (int kt = 0; kt < 2; kt++) {
        const float* e0 = sc[2 * kt];
        const float* e1 = sc[2 * kt + 1];
        split2(e0[0], e0[1], ph[kt][0], pl[kt][0]);
        split2(e0[2], e0[3], ph[kt][1], pl[kt][1]);
        split2(e1[0], e1[1], ph[kt][2], pl[kt][2]);
        split2(e1[2], e1[3], ph[kt][3], pl[kt][3]);
    }
}
// half of PV (4 ng): 8 LDSM + 24 HMMA
static __device__ __forceinline__ void pv_half(float oc[8][4], const uint32_t ph[2][4],
                                               const uint32_t pl[2][4], uint32_t slot,
                                               uint32_t vrow, int h) {
    const uint32_t vhb = slot + 2u * TILEB;
    const uint32_t vlb = slot + 3u * TILEB;
    uint32_t vh4[4][4], vl4[4][4];
#pragma unroll
    for (int j = 0; j < 4; j++) {
        uint32_t c = (uint32_t)(4 * h + j);
        uint32_t off = vrow * 128u + ((c ^ (vrow & 7u)) << 4);
        ldsm4t(vh4[j], vhb + off);
        ldsm4t(vl4[j], vlb + off);
    }
#pragma unroll
    for (int j = 0; j < 4; j++) mma16816(oc[4 * h + j], ph[0], &vh4[j][0]);
#pragma unroll
    for (int j = 0; j < 4; j++) mma16816(oc[4 * h + j], ph[1], &vh4[j][2]);
#pragma unroll
    for (int j = 0; j < 4; j++) mma16816(oc[4 * h + j], ph[0], &vl4[j][0]);
#pragma unroll
    for (int j = 0; j < 4; j++) mma16816(oc[4 * h + j], ph[1], &vl4[j][2]);
#pragma unroll
    for (int j = 0; j < 4; j++) mma16816(oc[4 * h + j], pl[0], &vh4[j][0]);
#pragma unroll
    for (int j = 0; j < 4; j++) mma16816(oc[4 * h + j], pl[1], &vh4[j][2]);
}
static __device__ __forceinline__ void soft_pv(float sc[4][4], float oc[8][4],
                                               float& lacc0, float& lacc1,
                                               uint32_t slot, uint32_t vrow) {
#pragma unroll
    for (int nt = 0; nt < 4; nt++) exp4(sc[nt], lacc0, lacc1);
    uint32_t ph[2][4], pl[2][4];
    split8(sc, ph, pl);
    pv_half(oc, ph, pl, slot, vrow, 0);
    pv_half(oc, ph, pl, slot, vrow, 1);
}

// ---------------- main attention kernel ----------------
__global__ void __launch_bounds__(256, 2)
attn_hmma(const float* __restrict__ Qg, float* __restrict__ Og)
{
    extern __shared__ char smp[];
    const uint32_t sb = smem_u32(smp);

    const int w  = 31 - (int)blockIdx.x;   // heavy windows first
    const int bh = blockIdx.y;
    const int n_iter = w + 4;
    const int t = threadIdx.x;
    const int lane = t & 31, wid = t >> 5;
    const int lr = lane & 7, g = lane >> 3;
    const int wp = wid >> 1;
    const size_t bho = (size_t)bh * LSEQ * HDIM;

    const uint32_t q_row  = (uint32_t)(16 * wid + (g & 1) * 8 + lr);
    const uint32_t q_xc   = (uint32_t)(g >> 1);
    const uint32_t k_row0 = (uint32_t)((g >> 1) * 8 + lr);
    const uint32_t k_row1 = k_row0 + 16u;
    const uint32_t k_xc   = (uint32_t)(g & 1);
    const uint32_t v_row  = (uint32_t)(g * 8 + lr);

    const size_t   kvbase = (size_t)bh * 128 * 4096;
    const size_t   g_toff = (size_t)t * 16;
    const uint32_t s_toff = SWZC(t >> 3, t & 7);

    const uint32_t mb_full  = sb + OFF_MB;        // full[0..2] at +0,8,16
    const uint32_t mb_empty = sb + OFF_MB + 24u;  // empty[0..2]

    // ---- stage Q: QH -> smem, QL -> pair-slot 2 block-B area (temp) ----
    {
        const float* qb = Qg + bho + (size_t)w * 128 * HDIM;
        const float scale = 0.125f * 1.44269504088896f;   // 1/8 * log2(e)
#pragma unroll
        for (int rep = 0; rep < 4; rep++) {
            int id = t + rep * 256;
            const float4* p4 = (const float4*)(qb + id * 8);
            float4 A = p4[0], B = p4[1];
            float v[8] = {A.x * scale, A.y * scale, A.z * scale, A.w * scale,
                          B.x * scale, B.y * scale, B.z * scale, B.w * scale};
            uint4 h, l; cvt8(v, h, l);
            uint32_t doff = SWZC(id >> 3, id & 7);
            *(uint4*)(smp + OFF_QH + doff) = h;
            *(uint4*)(smp + OFF_KV + 2u * PSLOTB + BLKB + doff) = l;   // QL temp
        }
    }
    if (t == 0) {
#pragma unroll
        for (int s = 0; s < 3; s++) {
            MBINIT(mb_full + 8u * s, 256u);
            MBINIT(mb_empty + 8u * s, 256u);
        }
    }
    __syncthreads();   // Q staged + mbarriers initialized, visible to all

    // ---- Q fragments (registers, whole kernel) ----
    uint32_t qh[4][4], ql[4][4];
#pragma unroll
    for (int kt = 0; kt < 4; kt++) {
        uint32_t off = q_row * 128u + (((q_xc + 2 * kt) ^ (q_row & 7u)) << 4);
        ldsm4(qh[kt], sb + OFF_QH + off);
        ldsm4(ql[kt], sb + OFF_KV + 2u * PSLOTB + BLKB + off);
    }
    __syncthreads();   // everyone done reading QL temp; safe to overwrite via cp

    // ---- prologue: fill pair-slots 0,1,2 with pairs 0,1,2 (per-block guards) ----
#pragma unroll
    for (int p = 0; p < 3; p++) {
        uint32_t ps = sb + OFF_KV + (uint32_t)p * PSLOTB;
#pragma unroll
        for (int k = 0; k < 2; k++) {
            int blk = 2 * p + k;
            if (blk < n_iter) {
                size_t go = kvbase + (size_t)colof(blk, w) * 4096 + g_toff;
                uint32_t d = ps + (uint32_t)k * BLKB + s_toff;
                CP16(d + 0u * TILEB, g_KH + go);
                CP16(d + 1u * TILEB, g_KL + go);
                CP16(d + 2u * TILEB, g_VH + go);
                CP16(d + 3u * TILEB, g_VL + go);
            }
        }
        CPARR(mb_full + 8u * p);   // arrives when this thread's copies complete
    }

    float oc[8][4];
#pragma unroll
    for (int nt = 0; nt < 8; nt++)
#pragma unroll
        for (int j = 0; j < 4; j++) oc[nt][j] = 0.f;
    float lacc0 = 0.f, lacc1 = 0.f;

    const int npairs = (n_iter + 1) >> 1;
    const int bulkN  = w >> 1;

    for (int di = 0; di < npairs; di++) {
        // ---- refill pair di+2 into slot (di+2)%3 (freed at iter di-1) ----
        if (di >= 1) {
            int tp = di + 2;
            if (tp < npairs) {
                int sp = tp % 3;
                mbar_wait(mb_empty + 8u * sp, (uint32_t)((di - 1) / 3) & 1u);
                uint32_t ps = sb + OFF_KV + (uint32_t)sp * PSLOTB;
#pragma unroll
                for (int k = 0; k < 2; k++) {
                    int blk = 2 * tp + k;
                    if (blk < n_iter) {
                        size_t go = kvbase + (size_t)colof(blk, w) * 4096 + g_toff;
                        uint32_t d = ps + (uint32_t)k * BLKB + s_toff;
                        CP16(d + 0u * TILEB, g_KH + go);
                        CP16(d + 1u * TILEB, g_KL + go);
                        CP16(d + 2u * TILEB, g_VH + go);
                        CP16(d + 3u * TILEB, g_VL + go);
                    }
                }
                CPARR(mb_full + 8u * sp);
            }
        }

        const int s = di % 3;
        mbar_wait(mb_full + 8u * s, (uint32_t)(di / 3) & 1u);   // data ready (acquire)

        const uint32_t slot_a = sb + OFF_KV + (uint32_t)s * PSLOTB;
        const uint32_t slot_b = slot_a + BLKB;
        const int a = 2 * di, b = a + 1;

        if (di < bulkN) {
            // ---- bulk: branch-free, MMA ⊕ softmax interleaved ----
            float sa[4][4], sbx[4][4];
#pragma unroll
            for (int nt = 0; nt < 4; nt++)
#pragma unroll
                for (int j = 0; j < 4; j++) { sa[nt][j] = 0.f; sbx[nt][j] = 0.f; }

            qk_block(sa, slot_a, k_row0, k_row1, k_xc, qh, ql);
#pragma unroll
            for (int kt = 0; kt < 4; kt++) {
                qk_step(sbx, slot_b, k_row0, k_row1, k_xc, kt, qh, ql);
                exp4(sa[kt], lacc0, lacc1);
            }
            uint32_t pha[2][4], pla[2][4];
            split8(sa, pha, pla);
            pv_half(oc, pha, pla, slot_a, v_row, 0);
            exp4(sbx[0], lacc0, lacc1);
            exp4(sbx[1], lacc0, lacc1);
            pv_half(oc, pha, pla, slot_a, v_row, 1);
            exp4(sbx[2], lacc0, lacc1);
            exp4(sbx[3], lacc0, lacc1);
            uint32_t phb[2][4], plb[2][4];
            split8(sbx, phb, plb);
            pv_half(oc, phb, plb, slot_b, v_row, 0);
            pv_half(oc, phb, plb, slot_b, v_row, 1);
        } else {
            // ---- tail: masked diagonal pair (arrivals stay outside the masks) ----
            const bool va = (a < w) || (wp >= (a - w));
            const bool vb = (b < n_iter) && ((b < w) || (wp >= (b - w)));
            float sa[4][4], sbx[4][4];
#pragma unroll
            for (int nt = 0; nt < 4; nt++)
#pragma unroll
                for (int j = 0; j < 4; j++) { sa[nt][j] = 0.f; sbx[nt][j] = 0.f; }
            if (va) qk_block(sa,  slot_a, k_row0, k_row1, k_xc, qh, ql);
            if (vb) qk_block(sbx, slot_b, k_row0, k_row1, k_xc, qh, ql);
            if (va) soft_pv(sa,  oc, lacc0, lacc1, slot_a, v_row);
            if (vb) soft_pv(sbx, oc, lacc0, lacc1, slot_b, v_row);
        }

        MARR(mb_empty + 8u * s);   // this thread done reading slot s
    }

    // ---- deferred row-sum reduction ----
    lacc0 += __shfl_xor_sync(0xffffffffu, lacc0, 1);
    lacc0 += __shfl_xor_sync(0xffffffffu, lacc0, 2);
    lacc1 += __shfl_xor_sync(0xffffffffu, lacc1, 1);
    lacc1 += __shfl_xor_sync(0xffffffffu, lacc1, 2);

    // ---- normalize + store ----
    float rl0 = 1.f / lacc0, rl1 = 1.f / lacc1;
    int row0 = w * 128 + 16 * wid + (lane >> 2);
    float* ob = Og + bho + (size_t)row0 * HDIM;
#pragma unroll
    for (int nt = 0; nt < 8; nt++) {
        int c = nt * 8 + 2 * (lane & 3);
        float2 aa, bb;
        aa.x = oc[nt][0] * rl0; aa.y = oc[nt][1] * rl0;
        bb.x = oc[nt][2] * rl1; bb.y = oc[nt][3] * rl1;
        *(float2*)(ob + c)            = aa;
        *(float2*)(ob + 8 * HDIM + c) = bb;
    }
}

extern "C" void kernel_launch(void* const* d_in, const int* in_sizes, int n_in,
                              void* d_out, int out_size)
{
    const float* Q = (const float*)d_in[0];
    const float* K = (const float*)d_in[1];
    const float* V = (const float*)d_in[2];
    // rows/cols/block inputs encode the fixed DeepSpeed layout; compiled in.
    cudaFuncSetAttribute(attn_hmma, cudaFuncAttributeMaxDynamicSharedMemorySize, SMEM_TOT);
    conv_kv<<<4096, 256>>>(K, V);
    dim3 grid(NWIN, BHN);
    attn_hmma<<<grid, 256, SMEM_TOT>>>(Q, (float*)d_out);
}

// round 17
// speedup vs baseline: 1.5644x; 1.5644x over previous
#include <cuda_runtime.h>
#include <cuda_bf16.h>
#include <cuda_fp16.h>
#include <stdint.h>
#include <math.h>

#define NWIN 32
#define BHN  32
#define LSEQ 4096
#define HDIM 64

// swizzled layout: 128B rows, SW128 XOR swizzle -> conflict-free LDSM
#define SWZC(row, c) (((uint32_t)(row)) * 128u + ((((uint32_t)(c)) ^ (((uint32_t)(row)) & 7u)) << 4))

// ---- smem layout (bytes) ----
#define OFF_QH  0u            // 128x64 bf16 swizzled (16KB)
#define OFF_KV  16384u        // 6-slot ring; slot = 3 tiles (KH, KL bf16, V fp16) x 4096B
#define TILEB   4096u
#define SLOTB   12288u        // 3*4096
#define SMEM_TOT (16384u + 6u*12288u)   // 90112; 2 CTAs = 176KB <= 228KB

// ---- global scratch: K bf16 hi/lo, V fp16 single ----
#define KVBYTES (32ull * 4096ull * 64ull * 2ull)
__device__ __align__(16) unsigned char g_KH[KVBYTES];
__device__ __align__(16) unsigned char g_KL[KVBYTES];
__device__ __align__(16) unsigned char g_V [KVBYTES];

static __device__ __forceinline__ uint32_t smem_u32(const void* p) {
    uint32_t a;
    asm("{ .reg .u64 t; cvta.to.shared.u64 t, %1; cvt.u32.u64 %0, t; }" : "=r"(a) : "l"(p));
    return a;
}
static __device__ __forceinline__ void ldsm4(uint32_t r[4], uint32_t a) {
    asm volatile("ldmatrix.sync.aligned.m8n8.x4.shared.b16 {%0,%1,%2,%3}, [%4];"
                 : "=r"(r[0]), "=r"(r[1]), "=r"(r[2]), "=r"(r[3]) : "r"(a));
}
static __device__ __forceinline__ void ldsm4t(uint32_t r[4], uint32_t a) {
    asm volatile("ldmatrix.sync.aligned.m8n8.x4.trans.shared.b16 {%0,%1,%2,%3}, [%4];"
                 : "=r"(r[0]), "=r"(r[1]), "=r"(r[2]), "=r"(r[3]) : "r"(a));
}
static __device__ __forceinline__ void mma16816(float* c, const uint32_t* a, const uint32_t* b) {
    asm volatile("mma.sync.aligned.m16n8k16.row.col.f32.bf16.bf16.f32 "
                 "{%0,%1,%2,%3}, {%4,%5,%6,%7}, {%8,%9}, {%0,%1,%2,%3};"
                 : "+f"(c[0]), "+f"(c[1]), "+f"(c[2]), "+f"(c[3])
                 : "r"(a[0]), "r"(a[1]), "r"(a[2]), "r"(a[3]), "r"(b[0]), "r"(b[1]));
}
static __device__ __forceinline__ void mma16816h(float* c, const uint32_t* a, const uint32_t* b) {
    asm volatile("mma.sync.aligned.m16n8k16.row.col.f32.f16.f16.f32 "
                 "{%0,%1,%2,%3}, {%4,%5,%6,%7}, {%8,%9}, {%0,%1,%2,%3};"
                 : "+f"(c[0]), "+f"(c[1]), "+f"(c[2]), "+f"(c[3])
                 : "r"(a[0]), "r"(a[1]), "r"(a[2]), "r"(a[3]), "r"(b[0]), "r"(b[1]));
}
static __device__ __forceinline__ float ex2f(float x) {
    float r; asm("ex2.approx.ftz.f32 %0, %1;" : "=f"(r) : "f"(x)); return r;
}
#define CP16(d, s)   asm volatile("cp.async.cg.shared.global [%0], [%1], 16;" :: "r"(d), "l"(s))
#define CP_COMMIT()  asm volatile("cp.async.commit_group;" ::: "memory")
#define CP_WAIT2()   asm volatile("cp.async.wait_group 2;" ::: "memory")

static __device__ __forceinline__ uint32_t packh2(float a, float b) {
    __half2 h = __floats2half2_rn(a, b);
    return *(uint32_t*)&h;
}
static __device__ __forceinline__ void split2(float a, float b, uint32_t& hi, uint32_t& lo) {
    __nv_bfloat16 ha = __float2bfloat16_rn(a), hb = __float2bfloat16_rn(b);
    float ra = a - __bfloat162float(ha), rb = b - __bfloat162float(hb);
    __nv_bfloat16 la = __float2bfloat16_rn(ra), lb = __float2bfloat16_rn(rb);
    hi = (uint32_t)__bfloat16_as_ushort(ha) | ((uint32_t)__bfloat16_as_ushort(hb) << 16);
    lo = (uint32_t)__bfloat16_as_ushort(la) | ((uint32_t)__bfloat16_as_ushort(lb) << 16);
}
static __device__ __forceinline__ void cvt8(const float* v, uint4& h, uint4& l) {
    uint32_t hh[4], ll[4];
#pragma unroll
    for (int j = 0; j < 4; j++) split2(v[2 * j], v[2 * j + 1], hh[j], ll[j]);
    h = make_uint4(hh[0], hh[1], hh[2], hh[3]);
    l = make_uint4(ll[0], ll[1], ll[2], ll[3]);
}
static __device__ __forceinline__ void cvt8h(const float* v, uint4& h) {
    h = make_uint4(packh2(v[0], v[1]), packh2(v[2], v[3]),
                   packh2(v[4], v[5]), packh2(v[6], v[7]));
}

// ---------------- pre-pass: K -> bf16 hi/lo, V -> fp16 single ----------------
__global__ void __launch_bounds__(256)
conv_kv(const float* __restrict__ K, const float* __restrict__ V)
{
    size_t id = (size_t)blockIdx.x * 256 + threadIdx.x;
    {
        const float4* kp = (const float4*)(K + id * 8);
        float4 A = kp[0], B = kp[1];
        float v[8] = {A.x, A.y, A.z, A.w, B.x, B.y, B.z, B.w};
        uint4 h, l; cvt8(v, h, l);
        *(uint4*)(g_KH + id * 16) = h;
        *(uint4*)(g_KL + id * 16) = l;
    }
    {
        const float4* vp = (const float4*)(V + id * 8);
        float4 A = vp[0], B = vp[1];
        float v[8] = {A.x, A.y, A.z, A.w, B.x, B.y, B.z, B.w};
        uint4 h; cvt8h(v, h);
        *(uint4*)(g_V + id * 16) = h;
    }
}

static __device__ __forceinline__ int colof(int i, int w) {
    return (i < w) ? (4 * i + 3) : (4 * w + (i - w));
}

// one K-dim step (16 of 64) of QK for one block: 4 LDSM + 12 bf16 HMMA
static __device__ __forceinline__ void qk_step(float sc[4][4], uint32_t slot,
                                               uint32_t krow0, uint32_t krow1, uint32_t kxc,
                                               int kt, const uint32_t qh[4][4],
                                               const uint32_t ql[4][4]) {
    uint32_t c0 = kxc + 2u * (uint32_t)kt;
    uint32_t a0 = slot + krow0 * 128u + ((c0 ^ (krow0 & 7u)) << 4);
    uint32_t a1 = slot + krow1 * 128u + ((c0 ^ (krow1 & 7u)) << 4);
    uint32_t bh0[4], bh1[4], bl0[4], bl1[4];
    ldsm4(bh0, a0);            // KH ntiles 0,1
    ldsm4(bh1, a1);            // KH ntiles 2,3
    ldsm4(bl0, a0 + TILEB);    // KL
    ldsm4(bl1, a1 + TILEB);
    mma16816(sc[0], qh[kt], &bh0[0]);  mma16816(sc[1], qh[kt], &bh0[2]);
    mma16816(sc[2], qh[kt], &bh1[0]);  mma16816(sc[3], qh[kt], &bh1[2]);
    mma16816(sc[0], qh[kt], &bl0[0]);  mma16816(sc[1], qh[kt], &bl0[2]);
    mma16816(sc[2], qh[kt], &bl1[0]);  mma16816(sc[3], qh[kt], &bl1[2]);
    mma16816(sc[0], ql[kt], &bh0[0]);  mma16816(sc[1], ql[kt], &bh0[2]);
    mma16816(sc[2], ql[kt], &bh1[0]);  mma16816(sc[3], ql[kt], &bh1[2]);
}
static __device__ __forceinline__ void qk_block(float sc[4][4], uint32_t slot,
                                                uint32_t krow0, uint32_t krow1, uint32_t kxc,
                                                const uint32_t qh[4][4], const uint32_t ql[4][4]) {
#pragma unroll
    for (int kt = 0; kt < 4; kt++) qk_step(sc, slot, krow0, krow1, kxc, kt, qh, ql);
}

static __device__ __forceinline__ void exp4(float* s, float& l0, float& l1) {
    s[0] = ex2f(s[0]); s[1] = ex2f(s[1]);
    s[2] = ex2f(s[2]); s[3] = ex2f(s[3]);
    l0 += s[0] + s[1]; l1 += s[2] + s[3];
}
// P (16 fp32) -> fp16 A-fragments, same layout as before (8 packs, no residuals)
static __device__ __forceinline__ void pack8(const float sc[4][4], uint32_t p[2][4]) {
#pragma unroll
    for (int kt = 0; kt < 2; kt++) {
        const float* e0 = sc[2 * kt];
        const float* e1 = sc[2 * kt + 1];
        p[kt][0] = packh2(e0[0], e0[1]);
        p[kt][1] = packh2(e0[2], e0[3]);
        p[kt][2] = packh2(e1[0], e1[1]);
        p[kt][3] = packh2(e1[2], e1[3]);
    }
}
// half of PV (4 ng): 4 LDSM + 8 fp16 HMMA (single V term)
static __device__ __forceinline__ void pv_half(float oc[8][4], const uint32_t p[2][4],
                                               uint32_t slot, uint32_t vrow, int h) {
    const uint32_t vb = slot + 2u * TILEB;
    uint32_t v4[4][4];
#pragma unroll
    for (int j = 0; j < 4; j++) {
        uint32_t c = (uint32_t)(4 * h + j);
        uint32_t off = vrow * 128u + ((c ^ (vrow & 7u)) << 4);
        ldsm4t(v4[j], vb + off);
    }
#pragma unroll
    for (int j = 0; j < 4; j++) mma16816h(oc[4 * h + j], p[0], &v4[j][0]);
#pragma unroll
    for (int j = 0; j < 4; j++) mma16816h(oc[4 * h + j], p[1], &v4[j][2]);
}
static __device__ __forceinline__ void soft_pv(float sc[4][4], float oc[8][4],
                                               float& lacc0, float& lacc1,
                                               uint32_t slot, uint32_t vrow) {
#pragma unroll
    for (int nt = 0; nt < 4; nt++) exp4(sc[nt], lacc0, lacc1);
    uint32_t p[2][4];
    pack8(sc, p);
    pv_half(oc, p, slot, vrow, 0);
    pv_half(oc, p, slot, vrow, 1);
}

// ---------------- main attention kernel ----------------
__global__ void __launch_bounds__(256, 2)
attn_hmma(const float* __restrict__ Qg, float* __restrict__ Og)
{
    extern __shared__ char smp[];
    const uint32_t sb = smem_u32(smp);

    const int w  = 31 - (int)blockIdx.x;   // heavy windows first
    const int bh = blockIdx.y;
    const int n_iter = w + 4;
    const int t = threadIdx.x;
    const int lane = t & 31, wid = t >> 5;
    const int lr = lane & 7, g = lane >> 3;
    const int wp = wid >> 1;               // warp pair = 32-row block index
    const size_t bho = (size_t)bh * LSEQ * HDIM;

    const uint32_t q_row  = (uint32_t)(16 * wid + (g & 1) * 8 + lr);
    const uint32_t q_xc   = (uint32_t)(g >> 1);
    const uint32_t k_row0 = (uint32_t)((g >> 1) * 8 + lr);
    const uint32_t k_row1 = k_row0 + 16u;
    const uint32_t k_xc   = (uint32_t)(g & 1);
    const uint32_t v_row  = (uint32_t)(g * 8 + lr);

    const size_t   kvbase = (size_t)bh * 128 * 4096;
    const size_t   g_toff = (size_t)t * 16;
    const uint32_t s_toff = SWZC(t >> 3, t & 7);

    // ---- stage Q: QH -> smem, QL -> slots 4/5 region (16KB temp); scale folds 1/8*log2(e) ----
    {
        const float* qb = Qg + bho + (size_t)w * 128 * HDIM;
        const float scale = 0.125f * 1.44269504088896f;
#pragma unroll
        for (int rep = 0; rep < 4; rep++) {
            int id = t + rep * 256;
            const float4* p4 = (const float4*)(qb + id * 8);
            float4 A = p4[0], B = p4[1];
            float v[8] = {A.x * scale, A.y * scale, A.z * scale, A.w * scale,
                          B.x * scale, B.y * scale, B.z * scale, B.w * scale};
            uint4 h, l; cvt8(v, h, l);
            uint32_t doff = SWZC(id >> 3, id & 7);
            *(uint4*)(smp + OFF_QH + doff) = h;
            *(uint4*)(smp + OFF_KV + 4u * SLOTB + doff) = l;   // QL temp in slots 4/5
        }
    }

    // ---- prologue: issue cp for blocks 0..3 into slots 0..3 ----
#pragma unroll
    for (int s = 0; s < 4; s++) {
        size_t go = kvbase + (size_t)colof(s, w) * 4096 + g_toff;
        uint32_t d = sb + OFF_KV + (uint32_t)s * SLOTB + s_toff;
        CP16(d + 0u * TILEB, g_KH + go);
        CP16(d + 1u * TILEB, g_KL + go);
        CP16(d + 2u * TILEB, g_V  + go);
        CP_COMMIT();
    }
    CP_WAIT2();          // blocks 0,1 landed
    __syncthreads();     // Q staging + blocks 0,1 visible

    // ---- Q fragments (registers, whole kernel) ----
    uint32_t qh[4][4], ql[4][4];
#pragma unroll
    for (int kt = 0; kt < 4; kt++) {
        uint32_t off = q_row * 128u + (((q_xc + 2 * kt) ^ (q_row & 7u)) << 4);
        ldsm4(qh[kt], sb + OFF_QH + off);
        ldsm4(ql[kt], sb + OFF_KV + 4u * SLOTB + off);
    }

    float oc[8][4];
#pragma unroll
    for (int nt = 0; nt < 8; nt++)
#pragma unroll
        for (int j = 0; j < 4; j++) oc[nt][j] = 0.f;
    float lacc0 = 0.f, lacc1 = 0.f;

    const int npairs = (n_iter + 1) >> 1;
    const int bulkN  = w >> 1;     // pairs with both blocks unmasked for all warps

    // ================= bulk loop: branch-free, MMA ⊕ softmax interleaved =================
    for (int di = 0; di < bulkN; di++) {
        const int a = 2 * di, b = a + 1;
        CP_WAIT2();
        __syncthreads();   // blocks a,b ready; slots (a+4)%6,(b+4)%6 free (read finished last pair)

        // refill slots (a+4)%6, (b+4)%6 (always in range inside bulk)
#pragma unroll
        for (int k = 0; k < 2; k++) {
            int nb = a + 4 + k;
            size_t go = kvbase + (size_t)colof(nb, w) * 4096 + g_toff;
            uint32_t d = sb + OFF_KV + (uint32_t)(nb % 6) * SLOTB + s_toff;
            CP16(d + 0u * TILEB, g_KH + go);
            CP16(d + 1u * TILEB, g_KL + go);
            CP16(d + 2u * TILEB, g_V  + go);
            CP_COMMIT();
        }

        const uint32_t slot_a = sb + OFF_KV + (uint32_t)(a % 6) * SLOTB;
        const uint32_t slot_b = sb + OFF_KV + (uint32_t)(b % 6) * SLOTB;

        float sa[4][4], sbx[4][4];
#pragma unroll
        for (int nt = 0; nt < 4; nt++)
#pragma unroll
            for (int j = 0; j < 4; j++) { sa[nt][j] = 0.f; sbx[nt][j] = 0.f; }

        // QK(a)
        qk_block(sa, slot_a, k_row0, k_row1, k_xc, qh, ql);
        // QK(b) interleaved with exp(a)
#pragma unroll
        for (int kt = 0; kt < 4; kt++) {
            qk_step(sbx, slot_b, k_row0, k_row1, k_xc, kt, qh, ql);
            exp4(sa[kt], lacc0, lacc1);
        }
        // pack(a), PV(a) halves interleaved with exp(b)
        uint32_t pa[2][4];
        pack8(sa, pa);
        pv_half(oc, pa, slot_a, v_row, 0);
        exp4(sbx[0], lacc0, lacc1);
        exp4(sbx[1], lacc0, lacc1);
        pv_half(oc, pa, slot_a, v_row, 1);
        exp4(sbx[2], lacc0, lacc1);
        exp4(sbx[3], lacc0, lacc1);
        // pack(b) + PV(b)
        uint32_t pb[2][4];
        pack8(sbx, pb);
        pv_half(oc, pb, slot_b, v_row, 0);
        pv_half(oc, pb, slot_b, v_row, 1);
    }

    // ================= tail loop: masked diagonal pairs =================
    for (int di = bulkN; di < npairs; di++) {
        const int a = 2 * di, b = a + 1;
        CP_WAIT2();
        __syncthreads();

#pragma unroll
        for (int k = 0; k < 2; k++) {
            int nb = a + 4 + k;
            if (nb < n_iter) {
                size_t go = kvbase + (size_t)colof(nb, w) * 4096 + g_toff;
                uint32_t d = sb + OFF_KV + (uint32_t)(nb % 6) * SLOTB + s_toff;
                CP16(d + 0u * TILEB, g_KH + go);
                CP16(d + 1u * TILEB, g_KL + go);
                CP16(d + 2u * TILEB, g_V  + go);
            }
            CP_COMMIT();
        }

        const uint32_t slot_a = sb + OFF_KV + (uint32_t)(a % 6) * SLOTB;
        const uint32_t slot_b = sb + OFF_KV + (uint32_t)(b % 6) * SLOTB;
        const bool va = (a < w) || (wp >= (a - w));
        const bool vb = (b < n_iter) && ((b < w) || (wp >= (b - w)));

        float sa[4][4], sbx[4][4];
#pragma unroll
        for (int nt = 0; nt < 4; nt++)
#pragma unroll
            for (int j = 0; j < 4; j++) { sa[nt][j] = 0.f; sbx[nt][j] = 0.f; }

        if (va) qk_block(sa,  slot_a, k_row0, k_row1, k_xc, qh, ql);
        if (vb) qk_block(sbx, slot_b, k_row0, k_row1, k_xc, qh, ql);
        if (va) soft_pv(sa,  oc, lacc0, lacc1, slot_a, v_row);
        if (vb) soft_pv(sbx, oc, lacc0, lacc1, slot_b, v_row);
    }

    // ---- deferred row-sum reduction (quad lanes share a row) ----
    lacc0 += __shfl_xor_sync(0xffffffffu, lacc0, 1);
    lacc0 += __shfl_xor_sync(0xffffffffu, lacc0, 2);
    lacc1 += __shfl_xor_sync(0xffffffffu, lacc1, 1);
    lacc1 += __shfl_xor_sync(0xffffffffu, lacc1, 2);

    // ---- normalize + store ----
    float rl0 = 1.f / lacc0, rl1 = 1.f / lacc1;
    int row0 = w * 128 + 16 * wid + (lane >> 2);
    float* ob = Og + bho + (size_t)row0 * HDIM;
#pragma unroll
    for (int nt = 0; nt < 8; nt++) {
        int c = nt * 8 + 2 * (lane & 3);
        float2 aa, bb;
        aa.x = oc[nt][0] * rl0; aa.y = oc[nt][1] * rl0;
        bb.x = oc[nt][2] * rl1; bb.y = oc[nt][3] * rl1;
        *(float2*)(ob + c)            = aa;
        *(float2*)(ob + 8 * HDIM + c) = bb;
    }
}

extern "C" void kernel_launch(void* const* d_in, const int* in_sizes, int n_in,
                              void* d_out, int out_size)
{
    const float* Q = (const float*)d_in[0];
    const float* K = (const float*)d_in[1];
    const float* V = (const float*)d_in[2];
    // rows/cols/block inputs encode the fixed DeepSpeed layout; compiled in.
    cudaFuncSetAttribute(attn_hmma, cudaFuncAttributeMaxDynamicSharedMemorySize, SMEM_TOT);
    conv_kv<<<4096, 256>>>(K, V);
    dim3 grid(NWIN, BHN);
    attn_hmma<<<grid, 256, SMEM_TOT>>>(Q, (float*)d_out);
}